// round 1
// baseline (speedup 1.0000x reference)
#include <cuda_runtime.h>
#include <math.h>

#define BB 256
#define SS 4096
#define HH 64
#define GG 192   // 3*H

// Scratch: layer activations, in-place across layers, per-batch contiguous.
// buf[b][t][k] = g_buf[(b*SS + t)*HH + k]
__device__ float g_buf[(size_t)BB * SS * HH];      // 268 MB
__device__ float g_scores[(size_t)BB * 4 * SS];    // 16 MB

__device__ __forceinline__ float sigmoidf_(float x) {
    return 1.0f / (1.0f + __expf(-x));
}
__device__ __forceinline__ float tanhf_(float x) {
    x = fminf(fmaxf(x, -15.0f), 15.0f);
    float e = __expf(2.0f * x);
    return (e - 1.0f) / (e + 1.0f);
}

// ---------------------------------------------------------------------------
// GRU layer: one CTA = one batch element, 192 threads = one gate row each.
// Thread j owns row j of W_ih and W_hh (registers). h lives in smem (64 f).
// Per step: phase A computes both dots for all rows; r,z rows write
// sigmoid pre-gates to smem; barrier; phase B: n-rows finish tanh + h update,
// input-prefetch threads stage x_{t+1}; barrier.
// ---------------------------------------------------------------------------
template <bool FIRST>
__device__ void gru_layer(
    const float* __restrict__ wih, const float* __restrict__ whh,
    const float* __restrict__ bih, const float* __restrict__ bhh,
    const float* __restrict__ inp,   // FIRST: x + b*SS (scalar/step); else buf
    float* __restrict__ outp,        // buf (may alias inp; read t+2 < write t)
    float* sh, float (*sx)[HH], float* srz)
{
    const int j = threadIdx.x;
    constexpr int IN = FIRST ? 1 : HH;

    float wi[IN];
    float wh[HH];
#pragma unroll
    for (int k = 0; k < HH; k++) wh[k] = whh[j * HH + k];
#pragma unroll
    for (int k = 0; k < IN; k++) wi[k] = wih[j * IN + k];
    const float bi = bih[j];
    const float bh = bhh[j];

    if (j < HH) sh[j] = 0.0f;
    float xreg = 0.0f;
    if (j < IN) {
        sx[0][j] = inp[j];                 // t = 0
        xreg     = inp[(size_t)IN + j];    // t = 1 (held for next stage)
    }
    __syncthreads();

    for (int t = 0; t < SS; t++) {
        const int cur = t & 1;
        // ---- phase A: input dot + hidden dot ----
        float ai;
        if (FIRST) {
            ai = fmaf(wi[0], sx[cur][0], bi);
        } else {
            const float4* xv = (const float4*)sx[cur];
            float a0 = bi, a1 = 0.f, a2 = 0.f, a3 = 0.f;
#pragma unroll
            for (int kk = 0; kk < 16; kk++) {
                float4 v = xv[kk];
                a0 = fmaf(wi[4 * kk + 0], v.x, a0);
                a1 = fmaf(wi[4 * kk + 1], v.y, a1);
                a2 = fmaf(wi[4 * kk + 2], v.z, a2);
                a3 = fmaf(wi[4 * kk + 3], v.w, a3);
            }
            ai = (a0 + a1) + (a2 + a3);
        }
        float ah;
        {
            const float4* hv = (const float4*)sh;
            float a0 = bh, a1 = 0.f, a2 = 0.f, a3 = 0.f;
#pragma unroll
            for (int kk = 0; kk < 16; kk++) {
                float4 v = hv[kk];
                a0 = fmaf(wh[4 * kk + 0], v.x, a0);
                a1 = fmaf(wh[4 * kk + 1], v.y, a1);
                a2 = fmaf(wh[4 * kk + 2], v.z, a2);
                a3 = fmaf(wh[4 * kk + 3], v.w, a3);
            }
            ah = (a0 + a1) + (a2 + a3);
        }
        if (j < 128) srz[j] = sigmoidf_(ai + ah);   // r rows [0,64), z rows [64,128)
        __syncthreads();

        // ---- phase B ----
        if (j >= 128) {
            const int k = j - 128;
            float r = srz[k];
            float z = srz[64 + k];
            float n = tanhf_(fmaf(r, ah, ai));      // tanh(xn + r*hn), biases inside
            float hp = sh[k];
            float hn = fmaf(z, hp - n, n);          // (1-z)*n + z*h
            sh[k] = hn;
            outp[(size_t)t * HH + k] = hn;
        } else if (j < IN) {
            sx[1 - cur][j] = xreg;                  // stage x_{t+1}
            xreg = (t + 2 < SS) ? inp[(size_t)(t + 2) * IN + j] : 0.0f;
        }
        __syncthreads();
    }
}

__global__ __launch_bounds__(GG)
void gru_kernel(
    const float* __restrict__ x,
    const float* __restrict__ wih0, const float* __restrict__ whh0,
    const float* __restrict__ bih0, const float* __restrict__ bhh0,
    const float* __restrict__ wih1, const float* __restrict__ whh1,
    const float* __restrict__ bih1, const float* __restrict__ bhh1,
    const float* __restrict__ wih2, const float* __restrict__ whh2,
    const float* __restrict__ bih2, const float* __restrict__ bhh2)
{
    __shared__ __align__(16) float sh[HH];
    __shared__ __align__(16) float sx[2][HH];
    __shared__ float srz[128];

    const int b = blockIdx.x;
    float* buf = g_buf + (size_t)b * SS * HH;

    gru_layer<true >(wih0, whh0, bih0, bhh0, x + (size_t)b * SS, buf, sh, sx, srz);
    __syncthreads();
    gru_layer<false>(wih1, whh1, bih1, bhh1, buf, buf, sh, sx, srz);
    __syncthreads();
    gru_layer<false>(wih2, whh2, bih2, bhh2, buf, buf, sh, sx, srz);
}

// ---------------------------------------------------------------------------
// Attention + head. One CTA per batch element, 256 threads.
// scores[b,h,s] = g[b,h,:]·out[b,s,:] + c[b,h]  (Wk folded through q, /sqrt(16))
// ctx[b,hd]     = Wv[hd,:]·u[b,h,:] + bv[hd],  u = Σ_s softmax(s)·out[b,s,:]
// ---------------------------------------------------------------------------
__global__ __launch_bounds__(256)
void attn_kernel(
    const float* __restrict__ in_proj_w, const float* __restrict__ in_proj_b,
    const float* __restrict__ out_proj_w, const float* __restrict__ out_proj_b,
    const float* __restrict__ fc_w, const float* __restrict__ fc_b,
    float* __restrict__ out)
{
    const int b = blockIdx.x;
    const int tid = threadIdx.x;

    __shared__ __align__(16) float shl[HH];
    __shared__ __align__(16) float sq[HH];
    __shared__ __align__(16) float sg[4][HH];
    __shared__ float sc[4];
    __shared__ float sred[4][256];
    __shared__ float sm4[4], sl4[4];
    __shared__ __align__(16) float stile[64][HH];   // 16 KB
    __shared__ float sw[4][64];
    __shared__ float su[4][HH];
    __shared__ __align__(16) float sctx[HH];
    __shared__ float sao[HH];

    const float* mybuf = g_buf + (size_t)b * SS * HH;

    // last hidden state
    if (tid < HH) shl[tid] = mybuf[(size_t)(SS - 1) * HH + tid];
    __syncthreads();

    // q = Wq @ h_last + bq
    if (tid < HH) {
        float acc = in_proj_b[tid];
#pragma unroll
        for (int k = 0; k < HH; k++)
            acc = fmaf(in_proj_w[tid * HH + k], shl[k], acc);
        sq[tid] = acc;
    }
    __syncthreads();

    // g[h,e] = (1/4) * sum_d q[h*16+d] * Wk[h*16+d, e];  c[h] from bk
    if (tid < HH) {
#pragma unroll
        for (int h = 0; h < 4; h++) {
            float acc = 0.0f;
#pragma unroll
            for (int d = 0; d < 16; d++)
                acc = fmaf(sq[h * 16 + d], in_proj_w[(HH + h * 16 + d) * HH + tid], acc);
            sg[h][tid] = acc * 0.25f;
        }
    }
    if (tid < 4) {
        float acc = 0.0f;
#pragma unroll
        for (int d = 0; d < 16; d++)
            acc = fmaf(sq[tid * 16 + d], in_proj_b[HH + tid * 16 + d], acc);
        sc[tid] = acc * 0.25f;
    }
    __syncthreads();

    // ---- pass 1: scores + per-head max ----
    float mloc[4] = {-1e30f, -1e30f, -1e30f, -1e30f};
    for (int s = tid; s < SS; s += 256) {
        const float4* ov = (const float4*)(mybuf + (size_t)s * HH);
        float4 o[16];
#pragma unroll
        for (int kk = 0; kk < 16; kk++) o[kk] = ov[kk];
#pragma unroll
        for (int h = 0; h < 4; h++) {
            const float4* gv = (const float4*)sg[h];
            float a0 = sc[h], a1 = 0.f, a2 = 0.f, a3 = 0.f;
#pragma unroll
            for (int kk = 0; kk < 16; kk++) {
                float4 g4 = gv[kk];
                a0 = fmaf(g4.x, o[kk].x, a0);
                a1 = fmaf(g4.y, o[kk].y, a1);
                a2 = fmaf(g4.z, o[kk].z, a2);
                a3 = fmaf(g4.w, o[kk].w, a3);
            }
            float sv = (a0 + a1) + (a2 + a3);
            g_scores[((size_t)(b * 4 + h)) * SS + s] = sv;
            mloc[h] = fmaxf(mloc[h], sv);
        }
    }
#pragma unroll
    for (int h = 0; h < 4; h++) sred[h][tid] = mloc[h];
    __syncthreads();
    if (tid < 4) {
        float m = -1e30f;
        for (int i = 0; i < 256; i++) m = fmaxf(m, sred[tid][i]);
        sm4[tid] = m;
    }
    __syncthreads();

    // ---- pass 2: softmax weights + u accumulation (tiled over s) ----
    const int h = tid >> 6;
    const int e = tid & 63;
    const float mh = sm4[h];
    float uacc = 0.0f, lloc = 0.0f;

    for (int tile = 0; tile < SS / 64; tile++) {
        const int s0 = tile * 64;
        {   // stage out tile [64][64] coalesced
            float4* st4 = (float4*)stile;
            const float4* gv = (const float4*)(mybuf + (size_t)s0 * HH);
#pragma unroll
            for (int r = 0; r < 4; r++) {
                int idx = tid + r * 256;
                st4[idx] = gv[idx];
            }
        }
        {   // thread (h, sp=e): softmax weight
            float w = __expf(g_scores[((size_t)(b * 4 + h)) * SS + s0 + e] - mh);
            sw[h][e] = w;
            lloc += w;
        }
        __syncthreads();
#pragma unroll
        for (int sp = 0; sp < 64; sp++)
            uacc = fmaf(sw[h][sp], stile[sp][e], uacc);
        __syncthreads();
    }

    // reduce l per head
    ((float*)sred)[tid] = lloc;
    __syncthreads();
    if (tid < 4) {
        float l = 0.0f;
        for (int i = 0; i < 64; i++) l += ((float*)sred)[tid * 64 + i];
        sl4[tid] = l;
    }
    __syncthreads();

    su[h][e] = uacc / sl4[h];
    __syncthreads();

    // ctx[hd] = Wv[hd,:] @ u[h,:] + bv[hd]
    if (tid < HH) {
        const int hh = tid >> 4;
        float acc = in_proj_b[128 + tid];
#pragma unroll
        for (int k = 0; k < HH; k++)
            acc = fmaf(in_proj_w[(128 + tid) * HH + k], su[hh][k], acc);
        sctx[tid] = acc;
    }
    __syncthreads();

    // attn_out = out_proj @ ctx + b; partial logit
    if (tid < HH) {
        float acc = out_proj_b[tid];
#pragma unroll
        for (int k = 0; k < HH; k++)
            acc = fmaf(out_proj_w[tid * HH + k], sctx[k], acc);
        sao[tid] = fc_w[tid] * acc;
    }
    __syncthreads();

    if (tid == 0) {
        float lg = fc_b[0];
        for (int i = 0; i < HH; i++) lg += sao[i];
        out[b] = 1.0f / (1.0f + __expf(-lg));
    }
}

// ---------------------------------------------------------------------------
extern "C" void kernel_launch(void* const* d_in, const int* in_sizes, int n_in,
                              void* d_out, int out_size)
{
    const float* x    = (const float*)d_in[0];
    const float* wih0 = (const float*)d_in[1];
    const float* whh0 = (const float*)d_in[2];
    const float* bih0 = (const float*)d_in[3];
    const float* bhh0 = (const float*)d_in[4];
    const float* wih1 = (const float*)d_in[5];
    const float* whh1 = (const float*)d_in[6];
    const float* bih1 = (const float*)d_in[7];
    const float* bhh1 = (const float*)d_in[8];
    const float* wih2 = (const float*)d_in[9];
    const float* whh2 = (const float*)d_in[10];
    const float* bih2 = (const float*)d_in[11];
    const float* bhh2 = (const float*)d_in[12];
    const float* ipw  = (const float*)d_in[13];
    const float* ipb  = (const float*)d_in[14];
    const float* opw  = (const float*)d_in[15];
    const float* opb  = (const float*)d_in[16];
    const float* fcw  = (const float*)d_in[17];
    const float* fcb  = (const float*)d_in[18];

    gru_kernel<<<BB, GG>>>(x, wih0, whh0, bih0, bhh0,
                           wih1, whh1, bih1, bhh1,
                           wih2, whh2, bih2, bhh2);
    attn_kernel<<<BB, 256>>>(ipw, ipb, opw, opb, fcw, fcb, (float*)d_out);
}